// round 6
// baseline (speedup 1.0000x reference)
#include <cuda_runtime.h>
#include <cuda_bf16.h>

// DataWindowLoss: mean(|box5(x) - box5(y)|), x,y: [64,1,512,512] f32.
// box5(x)-box5(y) = box5(x-y); separable 5x5 uniform kernel.
// Interior row-chunks: cp.async smem pipeline (5 stages x 5 rows x {x,y}),
// 80KB of copies in flight per block with zero register cost; compute does
// horizontal 5-sums from smem float4 pairs and a vertical 5-row register
// ring. Boundary chunks + column-edge blocks use a guarded register path.

#define B_IMGS 64
#define H 512
#define W 512
#define W4 128
#define OH 516
#define OW 516

#define THREADS 128
#define CHUNK_ROWS 43
#define NCHUNK 12                       // 12*43 = 516 exactly
#define NBLOCKS ((NCHUNK + 1) * B_IMGS) // 832

#define STAGE_ROWS 5
#define NSTAGES 5
#define TOT_STAGES 10                   // ceil(47/5)
#define STAGE_F4 (STAGE_ROWS * W4)      // 640 float4 per tensor per stage
#define SMEM_BYTES (NSTAGES * STAGE_F4 * 2 * 16)   // 102400

__device__ double g_accum;      // zero-initialized
__device__ unsigned g_count;    // zero-initialized

__device__ __forceinline__ float warp_red(float v) {
    #pragma unroll
    for (int o = 16; o > 0; o >>= 1) v += __shfl_down_sync(0xffffffffu, v, o);
    return v;
}

__device__ __forceinline__ float4 f4zero() { return make_float4(0.f, 0.f, 0.f, 0.f); }

__device__ __forceinline__ void cp16(float4* dst, const float4* src) {
    unsigned d = (unsigned)__cvta_generic_to_shared(dst);
    asm volatile("cp.async.cg.shared.global [%0], [%1], 16;\n" :: "r"(d), "l"(src));
}
__device__ __forceinline__ void cp_commit() {
    asm volatile("cp.async.commit_group;\n");
}
template <int N> __device__ __forceinline__ void cp_wait() {
    asm volatile("cp.async.wait_group %0;\n" :: "n"(N));
}

// ---- guarded register-streaming path (boundary chunks) ----
__device__ __forceinline__ float scan_chunk_guard(const float4* __restrict__ x4,
                                                  const float4* __restrict__ y4,
                                                  int base_r, int g, int imax) {
    const int   gp    = (g > 0) ? (g - 1) : 0;
    const float gmask = (g > 0) ? 1.f : 0.f;

    float4 ring[5];
    #pragma unroll
    for (int k = 0; k < 5; ++k) ring[k] = f4zero();
    float4 vs = f4zero();
    float acc = 0.f;

    #pragma unroll 1
    for (int ib = 0; ib < 50; ib += 5) {
        #pragma unroll
        for (int j = 0; j < 5; ++j) {
            const int i = ib + j;
            const int r = base_r + i;
            const int rc = min(max(r, 0), H - 1);
            const float rmask = (r >= 0 && r < H) ? 1.f : 0.f;
            const size_t ro = (size_t)rc * W4;
            const float4 a  = x4[ro + g];
            const float4 b  = y4[ro + g];
            const float4 ap = x4[ro + gp];
            const float4 bp = y4[ro + gp];

            float4 cur, prv;
            cur.x = (a.x - b.x) * rmask; cur.y = (a.y - b.y) * rmask;
            cur.z = (a.z - b.z) * rmask; cur.w = (a.w - b.w) * rmask;
            const float pm = gmask * rmask;
            prv.x = (ap.x - bp.x) * pm; prv.y = (ap.y - bp.y) * pm;
            prv.z = (ap.z - bp.z) * pm; prv.w = (ap.w - bp.w) * pm;

            float4 hv;
            const float p23 = prv.z + prv.w;
            const float c01 = cur.x + cur.y;
            hv.x = prv.x + prv.y + p23 + cur.x;
            hv.y = prv.y + p23 + c01;
            hv.z = p23 + c01 + cur.z;
            hv.w = prv.w + c01 + cur.z + cur.w;

            vs.x += hv.x - ring[j].x; vs.y += hv.y - ring[j].y;
            vs.z += hv.z - ring[j].z; vs.w += hv.w - ring[j].w;
            ring[j] = hv;

            if (i >= 4 && i <= imax)
                acc += fabsf(vs.x) + fabsf(vs.y) + fabsf(vs.z) + fabsf(vs.w);
        }
    }
    return acc;
}

__global__ void __launch_bounds__(THREADS)
box_abs_kernel(const float* __restrict__ x, const float* __restrict__ y,
               float* __restrict__ out) {
    extern __shared__ float4 smem[];
    float4* smx = smem;                              // NSTAGES*STAGE_F4
    float4* smy = smem + NSTAGES * STAGE_F4;

    const int tid  = threadIdx.x;
    const int lane = tid & 31;
    const int img  = blockIdx.y;
    const size_t ibase = (size_t)img * H * W4;
    const float4* x4 = reinterpret_cast<const float4*>(x) + ibase;
    const float4* y4 = reinterpret_cast<const float4*>(y) + ibase;

    float acc = 0.f;

    if (blockIdx.x < NCHUNK) {
        const int ci     = blockIdx.x;
        const int R0     = ci * CHUNK_ROWS;
        const int base_r = R0 - 4;

        if (ci >= 1 && ci <= NCHUNK - 2) {
            // ---- interior: cp.async pipeline ----
            const int   u     = tid;
            const int   up    = (u > 0) ? (u - 1) : 0;
            const float gmask = (u > 0) ? 1.f : 0.f;

            // prologue: stages 0..NSTAGES-2
            #pragma unroll
            for (int k = 0; k < NSTAGES - 1; ++k) {
                const float4* gx = x4 + (size_t)(base_r + k * STAGE_ROWS) * W4;
                const float4* gy = y4 + (size_t)(base_r + k * STAGE_ROWS) * W4;
                float4* dx = smx + k * STAGE_F4;
                float4* dy = smy + k * STAGE_F4;
                #pragma unroll
                for (int i = 0; i < STAGE_ROWS; ++i) {
                    cp16(dx + i * W4 + tid, gx + i * W4 + tid);
                    cp16(dy + i * W4 + tid, gy + i * W4 + tid);
                }
                cp_commit();
            }

            float4 ring[5];
            #pragma unroll
            for (int k = 0; k < 5; ++k) ring[k] = f4zero();
            float4 vs = f4zero();

            #pragma unroll 1
            for (int k = 0; k < TOT_STAGES; ++k) {
                // issue stage k+NSTAGES-1 (slot freed at end of iter k-1)
                const int kn = k + NSTAGES - 1;
                if (kn < TOT_STAGES) {
                    const int slot = kn % NSTAGES;
                    const float4* gx = x4 + (size_t)(base_r + kn * STAGE_ROWS) * W4;
                    const float4* gy = y4 + (size_t)(base_r + kn * STAGE_ROWS) * W4;
                    float4* dx = smx + slot * STAGE_F4;
                    float4* dy = smy + slot * STAGE_F4;
                    #pragma unroll
                    for (int i = 0; i < STAGE_ROWS; ++i) {
                        cp16(dx + i * W4 + tid, gx + i * W4 + tid);
                        cp16(dy + i * W4 + tid, gy + i * W4 + tid);
                    }
                }
                cp_commit();               // exactly one group per iteration
                cp_wait<NSTAGES - 1>();    // stage k complete
                __syncthreads();

                const int slot = k % NSTAGES;
                const float4* sxs = smx + slot * STAGE_F4;
                const float4* sys = smy + slot * STAGE_F4;
                #pragma unroll
                for (int j = 0; j < STAGE_ROWS; ++j) {
                    const int i = k * STAGE_ROWS + j;
                    if (i < 47) {
                        const float4 a  = sxs[j * W4 + u];
                        const float4 b  = sys[j * W4 + u];
                        const float4 ap = sxs[j * W4 + up];
                        const float4 bp = sys[j * W4 + up];

                        float4 cur, prv;
                        cur.x = a.x - b.x; cur.y = a.y - b.y;
                        cur.z = a.z - b.z; cur.w = a.w - b.w;
                        prv.x = (ap.x - bp.x) * gmask; prv.y = (ap.y - bp.y) * gmask;
                        prv.z = (ap.z - bp.z) * gmask; prv.w = (ap.w - bp.w) * gmask;

                        float4 hv;
                        const float p23 = prv.z + prv.w;
                        const float c01 = cur.x + cur.y;
                        hv.x = prv.x + prv.y + p23 + cur.x;
                        hv.y = prv.y + p23 + c01;
                        hv.z = p23 + c01 + cur.z;
                        hv.w = prv.w + c01 + cur.z + cur.w;

                        vs.x += hv.x - ring[j].x; vs.y += hv.y - ring[j].y;
                        vs.z += hv.z - ring[j].z; vs.w += hv.w - ring[j].w;
                        ring[j] = hv;

                        if (i >= 4)
                            acc += fabsf(vs.x) + fabsf(vs.y) +
                                   fabsf(vs.z) + fabsf(vs.w);
                    }
                }
                __syncthreads();           // slot free for reuse
            }
        } else {
            // ---- boundary chunks (top/bottom): guarded register path ----
            acc = scan_chunk_guard(x4, y4, base_r, tid, CHUNK_ROWS + 3);
        }
    } else {
        // ---- edge path: output cols 512..515 (need only d-group 127) ----
        for (int pass = 0; pass < 2; ++pass) {
            if (pass == 1 && tid != 0) break;
            const int a = (pass == 0) ? 4 * tid : 512;
            float hx[8], hy[8], hz[8], hw[8];
            #pragma unroll
            for (int k = 0; k < 8; ++k) {
                const int r = a - 4 + k;
                float4 d = f4zero();
                if (r >= 0 && r < H) {
                    float4 av = x4[(size_t)r * W4 + 127];
                    float4 bv = y4[(size_t)r * W4 + 127];
                    d.x = av.x - bv.x; d.y = av.y - bv.y;
                    d.z = av.z - bv.z; d.w = av.w - bv.w;
                }
                hx[k] = d.x + d.y + d.z + d.w;   // h[512]
                hy[k] = d.y + d.z + d.w;         // h[513]
                hz[k] = d.z + d.w;               // h[514]
                hw[k] = d.w;                     // h[515]
            }
            #pragma unroll
            for (int j = 0; j < 4; ++j) {
                float sx = 0.f, sy = 0.f, sz = 0.f, sw = 0.f;
                #pragma unroll
                for (int k = j; k < j + 5; ++k) {
                    sx += hx[k]; sy += hy[k]; sz += hz[k]; sw += hw[k];
                }
                acc += fabsf(sx) + fabsf(sy) + fabsf(sz) + fabsf(sw);
            }
        }
    }

    // ---- block reduce + fused finalize ----
    __shared__ float wsum[THREADS / 32];
    acc = warp_red(acc);
    if (lane == 0) wsum[tid >> 5] = acc;
    __syncthreads();
    if (tid == 0) {
        float v = 0.f;
        #pragma unroll
        for (int i = 0; i < THREADS / 32; ++i) v += wsum[i];
        atomicAdd(&g_accum, (double)v);
        __threadfence();
        unsigned prev_cnt = atomicAdd(&g_count, 1u);
        if (prev_cnt == NBLOCKS - 1) {
            __threadfence();
            double total = atomicAdd(&g_accum, 0.0);
            const double scale = 1.0 / (25.0 * (double)B_IMGS * (double)OH * (double)OW);
            out[0] = (float)(total * scale);
            g_accum = 0.0;          // reset for next graph replay
            __threadfence();
            g_count = 0u;
        }
    }
}

extern "C" void kernel_launch(void* const* d_in, const int* in_sizes, int n_in,
                              void* d_out, int out_size) {
    (void)in_sizes; (void)n_in; (void)out_size;
    const float* x = (const float*)d_in[0];
    const float* y = (const float*)d_in[1];
    float* out = (float*)d_out;

    cudaFuncSetAttribute(box_abs_kernel,
                         cudaFuncAttributeMaxDynamicSharedMemorySize, SMEM_BYTES);

    dim3 grid(NCHUNK + 1, B_IMGS);
    box_abs_kernel<<<grid, THREADS, SMEM_BYTES>>>(x, y, out);
}

// round 7
// speedup vs baseline: 1.1245x; 1.1245x over previous
#include <cuda_runtime.h>
#include <cuda_bf16.h>

// DataWindowLoss: mean(|box5(x) - box5(y)|), x,y: [64,1,512,512] f32.
// box5(x)-box5(y) = box5(x-y); separable 5x5 uniform kernel.
// Interior row-chunks: cp.async pipeline, 2-row stages x 5 slots (40KB smem,
// depth 3 in flight = 24KB/block), ONE __syncthreads per stage. Compute does
// horizontal 5-sums from smem float4 pairs (g and g-1) and a vertical 5-row
// register ring with static phases (5 stages = 10 rows unrolled per iter).
// Boundary chunks + column-edge blocks use a guarded register path.

#define B_IMGS 64
#define H 512
#define W 512
#define W4 128
#define OH 516
#define OW 516

#define THREADS 128
#define CHUNK_ROWS 43
#define NCHUNK 12                       // 12*43 = 516 exactly
#define NBLOCKS ((NCHUNK + 1) * B_IMGS) // 832

#define NSTAGES 5
#define STAGE_ROWS 2
#define COPY_STAGES 24                  // rows 0..47 copied (47 rows used)
#define SCAN_ROWS 47
#define STAGE_F4 (STAGE_ROWS * W4)      // 256 float4 per tensor per stage
#define SMEM_BYTES (NSTAGES * STAGE_F4 * 2 * 16)   // 40960

__device__ double g_accum;      // zero-initialized
__device__ unsigned g_count;    // zero-initialized

__device__ __forceinline__ float warp_red(float v) {
    #pragma unroll
    for (int o = 16; o > 0; o >>= 1) v += __shfl_down_sync(0xffffffffu, v, o);
    return v;
}

__device__ __forceinline__ float4 f4zero() { return make_float4(0.f, 0.f, 0.f, 0.f); }

__device__ __forceinline__ void cp16(float4* dst, const float4* src) {
    unsigned d = (unsigned)__cvta_generic_to_shared(dst);
    asm volatile("cp.async.cg.shared.global [%0], [%1], 16;\n" :: "r"(d), "l"(src));
}
__device__ __forceinline__ void cp_commit() {
    asm volatile("cp.async.commit_group;\n");
}
template <int N> __device__ __forceinline__ void cp_wait() {
    asm volatile("cp.async.wait_group %0;\n" :: "n"(N));
}

// ---- guarded register-streaming path (boundary chunks) ----
__device__ __forceinline__ float scan_chunk_guard(const float4* __restrict__ x4,
                                                  const float4* __restrict__ y4,
                                                  int base_r, int g, int imax) {
    const int   gp    = (g > 0) ? (g - 1) : 0;
    const float gmask = (g > 0) ? 1.f : 0.f;

    float4 ring[5];
    #pragma unroll
    for (int k = 0; k < 5; ++k) ring[k] = f4zero();
    float4 vs = f4zero();
    float acc = 0.f;

    #pragma unroll 1
    for (int ib = 0; ib < 50; ib += 5) {
        #pragma unroll
        for (int j = 0; j < 5; ++j) {
            const int i = ib + j;
            const int r = base_r + i;
            const int rc = min(max(r, 0), H - 1);
            const float rmask = (r >= 0 && r < H) ? 1.f : 0.f;
            const size_t ro = (size_t)rc * W4;
            const float4 a  = x4[ro + g];
            const float4 b  = y4[ro + g];
            const float4 ap = x4[ro + gp];
            const float4 bp = y4[ro + gp];

            float4 cur, prv;
            cur.x = (a.x - b.x) * rmask; cur.y = (a.y - b.y) * rmask;
            cur.z = (a.z - b.z) * rmask; cur.w = (a.w - b.w) * rmask;
            const float pm = gmask * rmask;
            prv.x = (ap.x - bp.x) * pm; prv.y = (ap.y - bp.y) * pm;
            prv.z = (ap.z - bp.z) * pm; prv.w = (ap.w - bp.w) * pm;

            float4 hv;
            const float p23 = prv.z + prv.w;
            const float c01 = cur.x + cur.y;
            hv.x = prv.x + prv.y + p23 + cur.x;
            hv.y = prv.y + p23 + c01;
            hv.z = p23 + c01 + cur.z;
            hv.w = prv.w + c01 + cur.z + cur.w;

            vs.x += hv.x - ring[j].x; vs.y += hv.y - ring[j].y;
            vs.z += hv.z - ring[j].z; vs.w += hv.w - ring[j].w;
            ring[j] = hv;

            if (i >= 4 && i <= imax)
                acc += fabsf(vs.x) + fabsf(vs.y) + fabsf(vs.z) + fabsf(vs.w);
        }
    }
    return acc;
}

__global__ void __launch_bounds__(THREADS)
box_abs_kernel(const float* __restrict__ x, const float* __restrict__ y,
               float* __restrict__ out) {
    extern __shared__ float4 smem[];
    float4* smx = smem;                       // NSTAGES * STAGE_F4
    float4* smy = smem + NSTAGES * STAGE_F4;

    const int tid  = threadIdx.x;
    const int lane = tid & 31;
    const int img  = blockIdx.y;
    const size_t ibase = (size_t)img * H * W4;
    const float4* x4 = reinterpret_cast<const float4*>(x) + ibase;
    const float4* y4 = reinterpret_cast<const float4*>(y) + ibase;

    float acc = 0.f;

    if (blockIdx.x < NCHUNK) {
        const int ci     = blockIdx.x;
        const int R0     = ci * CHUNK_ROWS;
        const int base_r = R0 - 4;

        if (ci >= 1 && ci <= NCHUNK - 2) {
            // ---- interior: cp.async pipeline ----
            const int   u_    = tid;
            const int   up    = (u_ > 0) ? (u_ - 1) : 0;
            const float gmask = (u_ > 0) ? 1.f : 0.f;

            // issue a 2-row stage s into slot s%NSTAGES
            #define ISSUE(s)                                                   \
            {                                                                  \
                const int slot_ = (s) % NSTAGES;                               \
                const float4* gx = x4 + (size_t)(base_r + 2 * (s)) * W4 + tid; \
                const float4* gy = y4 + (size_t)(base_r + 2 * (s)) * W4 + tid; \
                float4* dx = smx + slot_ * STAGE_F4 + tid;                     \
                float4* dy = smy + slot_ * STAGE_F4 + tid;                     \
                cp16(dx,      gx);                                             \
                cp16(dx + W4, gx + W4);                                        \
                cp16(dy,      gy);                                             \
                cp16(dy + W4, gy + W4);                                        \
            }

            // prologue: stages 0,1,2
            ISSUE(0) cp_commit();
            ISSUE(1) cp_commit();
            ISSUE(2) cp_commit();

            float4 ring[5];
            #pragma unroll
            for (int k = 0; k < 5; ++k) ring[k] = f4zero();
            float4 vs = f4zero();

            #pragma unroll 1
            for (int kb = 0; kb < 25; kb += 5) {
                #pragma unroll
                for (int uu = 0; uu < 5; ++uu) {
                    const int s  = kb + uu;       // compute stage
                    const int sn = s + 3;         // issue stage
                    if (sn < COPY_STAGES) ISSUE(sn)
                    cp_commit();
                    cp_wait<3>();
                    __syncthreads();

                    if (s < COPY_STAGES) {
                        const int slot = s % NSTAGES;
                        const float4* sxs = smx + slot * STAGE_F4;
                        const float4* sys = smy + slot * STAGE_F4;
                        #pragma unroll
                        for (int j = 0; j < STAGE_ROWS; ++j) {
                            const int i = 2 * s + j;
                            const int ph = (2 * uu + j) % 5;   // static
                            if (i < SCAN_ROWS) {
                                const float4 a  = sxs[j * W4 + u_];
                                const float4 b  = sys[j * W4 + u_];
                                const float4 ap = sxs[j * W4 + up];
                                const float4 bp = sys[j * W4 + up];

                                float4 cur, prv;
                                cur.x = a.x - b.x; cur.y = a.y - b.y;
                                cur.z = a.z - b.z; cur.w = a.w - b.w;
                                prv.x = (ap.x - bp.x) * gmask;
                                prv.y = (ap.y - bp.y) * gmask;
                                prv.z = (ap.z - bp.z) * gmask;
                                prv.w = (ap.w - bp.w) * gmask;

                                float4 hv;
                                const float p23 = prv.z + prv.w;
                                const float c01 = cur.x + cur.y;
                                hv.x = prv.x + prv.y + p23 + cur.x;
                                hv.y = prv.y + p23 + c01;
                                hv.z = p23 + c01 + cur.z;
                                hv.w = prv.w + c01 + cur.z + cur.w;

                                vs.x += hv.x - ring[ph].x;
                                vs.y += hv.y - ring[ph].y;
                                vs.z += hv.z - ring[ph].z;
                                vs.w += hv.w - ring[ph].w;
                                ring[ph] = hv;

                                if (i >= 4)
                                    acc += fabsf(vs.x) + fabsf(vs.y) +
                                           fabsf(vs.z) + fabsf(vs.w);
                            }
                        }
                    }
                }
            }
            #undef ISSUE
        } else {
            // ---- boundary chunks (top/bottom): guarded register path ----
            acc = scan_chunk_guard(x4, y4, base_r, tid, CHUNK_ROWS + 3);
        }
    } else {
        // ---- edge path: output cols 512..515 (need only d-group 127) ----
        for (int pass = 0; pass < 2; ++pass) {
            if (pass == 1 && tid != 0) break;
            const int a = (pass == 0) ? 4 * tid : 512;
            float hx[8], hy[8], hz[8], hw[8];
            #pragma unroll
            for (int k = 0; k < 8; ++k) {
                const int r = a - 4 + k;
                float4 d = f4zero();
                if (r >= 0 && r < H) {
                    float4 av = x4[(size_t)r * W4 + 127];
                    float4 bv = y4[(size_t)r * W4 + 127];
                    d.x = av.x - bv.x; d.y = av.y - bv.y;
                    d.z = av.z - bv.z; d.w = av.w - bv.w;
                }
                hx[k] = d.x + d.y + d.z + d.w;   // h[512]
                hy[k] = d.y + d.z + d.w;         // h[513]
                hz[k] = d.z + d.w;               // h[514]
                hw[k] = d.w;                     // h[515]
            }
            #pragma unroll
            for (int j = 0; j < 4; ++j) {
                float sx = 0.f, sy = 0.f, sz = 0.f, sw = 0.f;
                #pragma unroll
                for (int k = j; k < j + 5; ++k) {
                    sx += hx[k]; sy += hy[k]; sz += hz[k]; sw += hw[k];
                }
                acc += fabsf(sx) + fabsf(sy) + fabsf(sz) + fabsf(sw);
            }
        }
    }

    // ---- block reduce + fused finalize ----
    __shared__ float wsum[THREADS / 32];
    acc = warp_red(acc);
    if (lane == 0) wsum[tid >> 5] = acc;
    __syncthreads();
    if (tid == 0) {
        float v = 0.f;
        #pragma unroll
        for (int i = 0; i < THREADS / 32; ++i) v += wsum[i];
        atomicAdd(&g_accum, (double)v);
        __threadfence();
        unsigned prev_cnt = atomicAdd(&g_count, 1u);
        if (prev_cnt == NBLOCKS - 1) {
            __threadfence();
            double total = atomicAdd(&g_accum, 0.0);
            const double scale = 1.0 / (25.0 * (double)B_IMGS * (double)OH * (double)OW);
            out[0] = (float)(total * scale);
            g_accum = 0.0;          // reset for next graph replay
            __threadfence();
            g_count = 0u;
        }
    }
}

extern "C" void kernel_launch(void* const* d_in, const int* in_sizes, int n_in,
                              void* d_out, int out_size) {
    (void)in_sizes; (void)n_in; (void)out_size;
    const float* x = (const float*)d_in[0];
    const float* y = (const float*)d_in[1];
    float* out = (float*)d_out;

    dim3 grid(NCHUNK + 1, B_IMGS);
    box_abs_kernel<<<grid, THREADS, SMEM_BYTES>>>(x, y, out);
}

// round 8
// speedup vs baseline: 1.8577x; 1.6520x over previous
#include <cuda_runtime.h>
#include <cuda_bf16.h>

// DataWindowLoss: mean(|box5(x) - box5(y)|), x,y: [64,1,512,512] f32.
// box5(x)-box5(y) = box5(x-y); separable 5x5 uniform kernel.
// Register streaming with explicit 2-row prefetch ring (forces >=4 loads in
// flight per warp), one load pair per row (neighbor d-group via shfl; lane-0
// fixup via predicated LDG that only executes on 1/32 lanes and hits L1).
// 16-output-row chunks fully unrolled (static ring phases). Boundary chunks
// and cols 512..515 take small guarded paths.

#define B_IMGS 64
#define H 512
#define W 512
#define W4 128
#define OH 516
#define OW 516

#define THREADS 128
#define CHUNK_ROWS 16
#define SCAN 20
#define NCHUNK 33                        // 33*16 = 528 >= 516
#define NBLOCKS ((NCHUNK + 1) * B_IMGS)  // 2176

__device__ double g_accum;      // zero-initialized
__device__ unsigned g_count;    // zero-initialized

__device__ __forceinline__ float warp_red(float v) {
    #pragma unroll
    for (int o = 16; o > 0; o >>= 1) v += __shfl_down_sync(0xffffffffu, v, o);
    return v;
}

__device__ __forceinline__ float4 f4zero() { return make_float4(0.f, 0.f, 0.f, 0.f); }

// predicated 128-bit global load: no branch, returns zeros when !pred
__device__ __forceinline__ float4 ldg_pred(const float4* p, unsigned pred) {
    float4 v;
    asm volatile(
        "{\n\t"
        ".reg .pred p;\n\t"
        "setp.ne.u32 p, %5, 0;\n\t"
        "mov.f32 %0, 0f00000000;\n\t"
        "mov.f32 %1, 0f00000000;\n\t"
        "mov.f32 %2, 0f00000000;\n\t"
        "mov.f32 %3, 0f00000000;\n\t"
        "@p ld.global.nc.v4.f32 {%0,%1,%2,%3}, [%4];\n\t"
        "}"
        : "=f"(v.x), "=f"(v.y), "=f"(v.z), "=f"(v.w)
        : "l"(p), "r"(pred));
    return v;
}

// ---- guarded register path (boundary chunks), 20 scan rows ----
__device__ __forceinline__ float scan_chunk_guard(const float4* __restrict__ x4,
                                                  const float4* __restrict__ y4,
                                                  int base_r, int g, int imax) {
    const int   gp    = (g > 0) ? (g - 1) : 0;
    const float gmask = (g > 0) ? 1.f : 0.f;

    float4 ring[5];
    #pragma unroll
    for (int k = 0; k < 5; ++k) ring[k] = f4zero();
    float4 vs = f4zero();
    float acc = 0.f;

    #pragma unroll
    for (int i = 0; i < SCAN; ++i) {
        const int r = base_r + i;
        const int rc = min(max(r, 0), H - 1);
        const float rmask = (r >= 0 && r < H) ? 1.f : 0.f;
        const size_t ro = (size_t)rc * W4;
        const float4 a  = x4[ro + g];
        const float4 b  = y4[ro + g];
        const float4 ap = x4[ro + gp];
        const float4 bp = y4[ro + gp];

        float4 cur, prv;
        cur.x = (a.x - b.x) * rmask; cur.y = (a.y - b.y) * rmask;
        cur.z = (a.z - b.z) * rmask; cur.w = (a.w - b.w) * rmask;
        const float pm = gmask * rmask;
        prv.x = (ap.x - bp.x) * pm; prv.y = (ap.y - bp.y) * pm;
        prv.z = (ap.z - bp.z) * pm; prv.w = (ap.w - bp.w) * pm;

        float4 hv;
        const float p23 = prv.z + prv.w;
        const float c01 = cur.x + cur.y;
        hv.x = prv.x + prv.y + p23 + cur.x;
        hv.y = prv.y + p23 + c01;
        hv.z = p23 + c01 + cur.z;
        hv.w = prv.w + c01 + cur.z + cur.w;

        const int ph = i % 5;
        vs.x += hv.x - ring[ph].x; vs.y += hv.y - ring[ph].y;
        vs.z += hv.z - ring[ph].z; vs.w += hv.w - ring[ph].w;
        ring[ph] = hv;

        if (i >= 4 && i <= imax)
            acc += fabsf(vs.x) + fabsf(vs.y) + fabsf(vs.z) + fabsf(vs.w);
    }
    return acc;
}

__global__ void __launch_bounds__(THREADS)
box_abs_kernel(const float* __restrict__ x, const float* __restrict__ y,
               float* __restrict__ out) {
    const int tid  = threadIdx.x;
    const int lane = tid & 31;
    const int img  = blockIdx.y;
    const size_t ibase = (size_t)img * H * W4;
    const float4* x4 = reinterpret_cast<const float4*>(x) + ibase;
    const float4* y4 = reinterpret_cast<const float4*>(y) + ibase;

    float acc = 0.f;

    if (blockIdx.x < NCHUNK) {
        const int ci     = blockIdx.x;
        const int R0     = ci * CHUNK_ROWS;
        const int base_r = R0 - 4;
        const bool interior = (base_r >= 0) && (base_r + SCAN - 1 < H);

        if (interior) {
            const int g = tid;
            const unsigned fixp = (lane == 0 && g > 0) ? 1u : 0u;
            const float4* px  = x4 + (size_t)base_r * W4 + g;
            const float4* py  = y4 + (size_t)base_r * W4 + g;
            const float4* pxm = px - 1;   // group g-1 (only read when fixp)
            const float4* pym = py - 1;

            // 2-slot prefetch ring
            float4 bx0 = px[0],       by0 = py[0];
            float4 bx1 = px[W4],      by1 = py[W4];

            float4 ring[5];
            #pragma unroll
            for (int k = 0; k < 5; ++k) ring[k] = f4zero();
            float4 vs = f4zero();

            #pragma unroll
            for (int i = 0; i < SCAN; ++i) {
                float4 a, b;
                if ((i & 1) == 0) { a = bx0; b = by0; }
                else              { a = bx1; b = by1; }
                // prefetch row i+2 into the slot just consumed
                if (i + 2 < SCAN) {
                    if ((i & 1) == 0) { bx0 = px[(i + 2) * W4]; by0 = py[(i + 2) * W4]; }
                    else              { bx1 = px[(i + 2) * W4]; by1 = py[(i + 2) * W4]; }
                }

                float4 cur;
                cur.x = a.x - b.x; cur.y = a.y - b.y;
                cur.z = a.z - b.z; cur.w = a.w - b.w;

                float4 prv;
                prv.x = __shfl_up_sync(0xffffffffu, cur.x, 1);
                prv.y = __shfl_up_sync(0xffffffffu, cur.y, 1);
                prv.z = __shfl_up_sync(0xffffffffu, cur.z, 1);
                prv.w = __shfl_up_sync(0xffffffffu, cur.w, 1);

                // lane-0 fixup: predicated loads (1/32 lanes, L1-resident line)
                const float4 fa = ldg_pred(pxm + i * W4, fixp);
                const float4 fb = ldg_pred(pym + i * W4, fixp);
                if (lane == 0) {
                    prv.x = fa.x - fb.x; prv.y = fa.y - fb.y;
                    prv.z = fa.z - fb.z; prv.w = fa.w - fb.w;
                }

                float4 hv;
                const float p23 = prv.z + prv.w;
                const float c01 = cur.x + cur.y;
                hv.x = prv.x + prv.y + p23 + cur.x;
                hv.y = prv.y + p23 + c01;
                hv.z = p23 + c01 + cur.z;
                hv.w = prv.w + c01 + cur.z + cur.w;

                const int ph = i % 5;
                vs.x += hv.x - ring[ph].x; vs.y += hv.y - ring[ph].y;
                vs.z += hv.z - ring[ph].z; vs.w += hv.w - ring[ph].w;
                ring[ph] = hv;

                if (i >= 4)
                    acc += fabsf(vs.x) + fabsf(vs.y) + fabsf(vs.z) + fabsf(vs.w);
            }
        } else {
            const int imax = min(SCAN - 1, OH - 1 - R0 + 4);
            acc = scan_chunk_guard(x4, y4, base_r, tid, imax);
        }
    } else {
        // ---- edge path: output cols 512..515 (need only d-group 127) ----
        for (int pass = 0; pass < 2; ++pass) {
            if (pass == 1 && tid != 0) break;
            const int a = (pass == 0) ? 4 * tid : 512;
            float hx[8], hy[8], hz[8], hw[8];
            #pragma unroll
            for (int k = 0; k < 8; ++k) {
                const int r = a - 4 + k;
                float4 d = f4zero();
                if (r >= 0 && r < H) {
                    float4 av = x4[(size_t)r * W4 + 127];
                    float4 bv = y4[(size_t)r * W4 + 127];
                    d.x = av.x - bv.x; d.y = av.y - bv.y;
                    d.z = av.z - bv.z; d.w = av.w - bv.w;
                }
                hx[k] = d.x + d.y + d.z + d.w;   // h[512]
                hy[k] = d.y + d.z + d.w;         // h[513]
                hz[k] = d.z + d.w;               // h[514]
                hw[k] = d.w;                     // h[515]
            }
            #pragma unroll
            for (int j = 0; j < 4; ++j) {
                float sx = 0.f, sy = 0.f, sz = 0.f, sw = 0.f;
                #pragma unroll
                for (int k = j; k < j + 5; ++k) {
                    sx += hx[k]; sy += hy[k]; sz += hz[k]; sw += hw[k];
                }
                acc += fabsf(sx) + fabsf(sy) + fabsf(sz) + fabsf(sw);
            }
        }
    }

    // ---- block reduce + fused finalize ----
    __shared__ float wsum[THREADS / 32];
    acc = warp_red(acc);
    if (lane == 0) wsum[tid >> 5] = acc;
    __syncthreads();
    if (tid == 0) {
        float v = 0.f;
        #pragma unroll
        for (int i = 0; i < THREADS / 32; ++i) v += wsum[i];
        atomicAdd(&g_accum, (double)v);
        __threadfence();
        unsigned prev_cnt = atomicAdd(&g_count, 1u);
        if (prev_cnt == NBLOCKS - 1) {
            __threadfence();
            double total = atomicAdd(&g_accum, 0.0);
            const double scale = 1.0 / (25.0 * (double)B_IMGS * (double)OH * (double)OW);
            out[0] = (float)(total * scale);
            g_accum = 0.0;          // reset for next graph replay
            __threadfence();
            g_count = 0u;
        }
    }
}

extern "C" void kernel_launch(void* const* d_in, const int* in_sizes, int n_in,
                              void* d_out, int out_size) {
    (void)in_sizes; (void)n_in; (void)out_size;
    const float* x = (const float*)d_in[0];
    const float* y = (const float*)d_in[1];
    float* out = (float*)d_out;

    dim3 grid(NCHUNK + 1, B_IMGS);
    box_abs_kernel<<<grid, THREADS>>>(x, y, out);
}